// round 1
// baseline (speedup 1.0000x reference)
#include <cuda_runtime.h>
#include <cstdint>
#include <math.h>

#define TT 256
#define BB 64
#define EE 256
#define HH 512
#define KK 32
#define G4H 2048
#define MROWS (TT*BB)          // 16384
#define WPAD 516               // padded smem row stride (floats) to avoid bank conflicts

// ---------------- scratch (static device allocations; no cudaMalloc anywhere) ----
__device__ float    g_x0[TT*BB*EE];          // embedded input      (T,B,E)
__device__ float    g_xpf[TT*BB*G4H];        // input proj fwd      (T,B,4H)
__device__ float    g_xpr[TT*BB*G4H];        // input proj rev      (T,B,4H)
__device__ float    g_hbuf[TT*BB*2*HH];      // layer output        (T,B,2H)
__device__ float    g_feats[TT*BB*KK];       // emissions           (T,B,K)
__device__ float    g_hstate[2*2*BB*HH];     // [buf][dir][B][H] double-buffered h
__device__ unsigned g_bar[2];                // per-direction barrier counters

// ---------------- small helpers --------------------------------------------------
__device__ __forceinline__ void ff2(unsigned long long &acc, unsigned long long a,
                                    unsigned long long b) {
    asm volatile("fma.rn.f32x2 %0, %1, %2, %0;" : "+l"(acc) : "l"(a), "l"(b));
}
__device__ __forceinline__ float hsum2(unsigned long long a) {
    float lo, hi;
    asm("mov.b64 {%0,%1}, %2;" : "=f"(lo), "=f"(hi) : "l"(a));
    return lo + hi;
}
__device__ __forceinline__ float sigm(float x) { return 1.0f / (1.0f + expf(-x)); }

// ---------------- embedding gather ----------------------------------------------
__global__ void embed_kernel(const int* __restrict__ sent, const float* __restrict__ emb,
                             float* __restrict__ x0) {
    int i = blockIdx.x * blockDim.x + threadIdx.x;      // over T*B*(E/4)
    int total = TT * BB * (EE / 4);
    if (i >= total) return;
    int tb = i >> 6;          // E/4 = 64
    int e4 = i & 63;
    int v = sent[tb];
    reinterpret_cast<float4*>(x0)[i] =
        reinterpret_cast<const float4*>(emb + (size_t)v * EE)[e4];
}

// ---------------- SGEMM: C(M,N) = A(M,K) @ W(N,K)^T + b1(N) + b2(N) --------------
// 128x128 block tile, BK=8, 256 threads, 8x8 per-thread micro-tile.
__global__ __launch_bounds__(256) void sgemm_nt_bias(
    const float* __restrict__ A, const float* __restrict__ W,
    const float* __restrict__ b1, const float* __restrict__ b2,
    float* __restrict__ C, int M, int N, int K)
{
    __shared__ __align__(16) float As[8][128];
    __shared__ __align__(16) float Bs[8][128];
    const int tid  = threadIdx.x;
    const int bn   = blockIdx.x * 128;
    const int bm   = blockIdx.y * 128;
    const int lrow = tid >> 1;
    const int lkq  = (tid & 1) * 4;
    const float* Ap = A + (size_t)(bm + lrow) * K + lkq;
    const float* Wp = W + (size_t)(bn + lrow) * K + lkq;
    const int tx = tid & 15;
    const int ty = tid >> 4;

    float acc[8][8];
    #pragma unroll
    for (int i = 0; i < 8; i++)
        #pragma unroll
        for (int j = 0; j < 8; j++) acc[i][j] = 0.0f;

    for (int kt = 0; kt < K; kt += 8) {
        float4 a = *reinterpret_cast<const float4*>(Ap + kt);
        float4 w = *reinterpret_cast<const float4*>(Wp + kt);
        As[lkq + 0][lrow] = a.x; As[lkq + 1][lrow] = a.y;
        As[lkq + 2][lrow] = a.z; As[lkq + 3][lrow] = a.w;
        Bs[lkq + 0][lrow] = w.x; Bs[lkq + 1][lrow] = w.y;
        Bs[lkq + 2][lrow] = w.z; Bs[lkq + 3][lrow] = w.w;
        __syncthreads();
        #pragma unroll
        for (int k = 0; k < 8; k++) {
            float af[8], bf[8];
            *reinterpret_cast<float4*>(af)     = *reinterpret_cast<const float4*>(&As[k][ty * 8]);
            *reinterpret_cast<float4*>(af + 4) = *reinterpret_cast<const float4*>(&As[k][ty * 8 + 4]);
            *reinterpret_cast<float4*>(bf)     = *reinterpret_cast<const float4*>(&Bs[k][tx * 8]);
            *reinterpret_cast<float4*>(bf + 4) = *reinterpret_cast<const float4*>(&Bs[k][tx * 8 + 4]);
            #pragma unroll
            for (int i = 0; i < 8; i++)
                #pragma unroll
                for (int j = 0; j < 8; j++)
                    acc[i][j] += af[i] * bf[j];
        }
        __syncthreads();
    }
    #pragma unroll
    for (int i = 0; i < 8; i++) {
        size_t row = (size_t)(bm + ty * 8 + i);
        #pragma unroll
        for (int j = 0; j < 8; j++) {
            int n = bn + tx * 8 + j;
            C[row * N + n] = acc[i][j] + b1[n] + b2[n];
        }
    }
}

// ---------------- persistent bidirectional LSTM layer ---------------------------
// Grid: 128 blocks (64/dir), 256 threads. Block `sub` owns 8 h-columns (all batch).
// W_hh slice (32 rows x 512) cached in smem for the whole sequence.
// h state double-buffered in global; per-direction software barrier each step.
#define LSTM_SMEM ((32 * WPAD + 64 * WPAD) * 4)

__global__ __launch_bounds__(256) void lstm_layer_kernel(
    const float* __restrict__ xpf, const float* __restrict__ xpr,
    const float* __restrict__ whf, const float* __restrict__ whr,
    float* __restrict__ hout, float* hstate, unsigned* bar)
{
    extern __shared__ __align__(16) float sm[];
    float* Wsm = sm;                 // [32][WPAD]
    float* Hsm = sm + 32 * WPAD;     // [64][WPAD]
    const int tid = threadIdx.x;
    const int dir = blockIdx.x >> 6;
    const int sub = blockIdx.x & 63;
    const int j0  = sub * 8;
    const float* W  = dir ? whr : whf;
    const float* xp = dir ? xpr : xpf;

    // cache W_hh slice once (rows {gate*512 + j0 + jl})
    for (int i = tid; i < 32 * 128; i += 256) {
        int r = i >> 7;
        int c = (i & 127) * 4;
        int gate = r >> 3, jl2 = r & 7;
        *reinterpret_cast<float4*>(&Wsm[r * WPAD + c]) =
            *reinterpret_cast<const float4*>(&W[(size_t)(gate * 512 + j0 + jl2) * HH + c]);
    }

    const int jl = tid & 7;
    const int b0 = tid >> 3;       // 0..31
    const int b1 = b0 + 32;
    const int j  = j0 + jl;
    float c0 = 0.0f, c1 = 0.0f;

    const ulonglong2* wip = reinterpret_cast<const ulonglong2*>(&Wsm[(0 * 8 + jl) * WPAD]);
    const ulonglong2* wfp = reinterpret_cast<const ulonglong2*>(&Wsm[(1 * 8 + jl) * WPAD]);
    const ulonglong2* wgp = reinterpret_cast<const ulonglong2*>(&Wsm[(2 * 8 + jl) * WPAD]);
    const ulonglong2* wop = reinterpret_cast<const ulonglong2*>(&Wsm[(3 * 8 + jl) * WPAD]);
    const ulonglong2* h0p = reinterpret_cast<const ulonglong2*>(&Hsm[b0 * WPAD]);
    const ulonglong2* h1p = reinterpret_cast<const ulonglong2*>(&Hsm[b1 * WPAD]);

    for (int s = 0; s < TT; s++) {
        const int rb = s & 1, wb = rb ^ 1;
        const float* hsrc = hstate + (size_t)(rb * 2 + dir) * (BB * HH);
        // broadcast previous h into smem (padded rows)
        for (int i = tid; i < BB * 128; i += 256) {
            int b = i >> 7;
            int c = (i & 127) * 4;
            *reinterpret_cast<float4*>(&Hsm[b * WPAD + c]) =
                *reinterpret_cast<const float4*>(&hsrc[b * HH + c]);
        }
        __syncthreads();

        unsigned long long aI0 = 0, aF0 = 0, aG0 = 0, aO0 = 0;
        unsigned long long aI1 = 0, aF1 = 0, aG1 = 0, aO1 = 0;
        #pragma unroll 4
        for (int k = 0; k < 128; k++) {
            ulonglong2 h0 = h0p[k], h1 = h1p[k];
            ulonglong2 wi = wip[k], wf = wfp[k], wg = wgp[k], wo = wop[k];
            ff2(aI0, wi.x, h0.x); ff2(aI0, wi.y, h0.y);
            ff2(aF0, wf.x, h0.x); ff2(aF0, wf.y, h0.y);
            ff2(aG0, wg.x, h0.x); ff2(aG0, wg.y, h0.y);
            ff2(aO0, wo.x, h0.x); ff2(aO0, wo.y, h0.y);
            ff2(aI1, wi.x, h1.x); ff2(aI1, wi.y, h1.y);
            ff2(aF1, wf.x, h1.x); ff2(aF1, wf.y, h1.y);
            ff2(aG1, wg.x, h1.x); ff2(aG1, wg.y, h1.y);
            ff2(aO1, wo.x, h1.x); ff2(aO1, wo.y, h1.y);
        }

        const int tt = dir ? (TT - 1 - s) : s;
        const float* xpt = xp + (size_t)tt * BB * G4H;
        float gi0 = xpt[b0 * G4H + 0 * HH + j] + hsum2(aI0);
        float gf0 = xpt[b0 * G4H + 1 * HH + j] + hsum2(aF0);
        float gg0 = xpt[b0 * G4H + 2 * HH + j] + hsum2(aG0);
        float go0 = xpt[b0 * G4H + 3 * HH + j] + hsum2(aO0);
        float gi1 = xpt[b1 * G4H + 0 * HH + j] + hsum2(aI1);
        float gf1 = xpt[b1 * G4H + 1 * HH + j] + hsum2(aF1);
        float gg1 = xpt[b1 * G4H + 2 * HH + j] + hsum2(aG1);
        float go1 = xpt[b1 * G4H + 3 * HH + j] + hsum2(aO1);

        c0 = sigm(gf0) * c0 + sigm(gi0) * tanhf(gg0);
        float h0v = sigm(go0) * tanhf(c0);
        c1 = sigm(gf1) * c1 + sigm(gi1) * tanhf(gg1);
        float h1v = sigm(go1) * tanhf(c1);

        float* hdst = hstate + (size_t)(wb * 2 + dir) * (BB * HH);
        hdst[b0 * HH + j] = h0v;
        hdst[b1 * HH + j] = h1v;
        float* op = hout + (size_t)tt * BB * (2 * HH) + (size_t)dir * HH;
        op[(size_t)b0 * (2 * HH) + j] = h0v;
        op[(size_t)b1 * (2 * HH) + j] = h1v;

        __syncthreads();
        if (s + 1 < TT) {
            if (tid == 0) {
                __threadfence();
                atomicAdd(&bar[dir], 1u);
                unsigned target = 64u * (unsigned)(s + 1);
                volatile unsigned* p = bar + dir;
                while (*p < target) __nanosleep(64);
                __threadfence();
            }
            __syncthreads();
        }
    }
}

// ---------------- emissions: feats = hbuf @ W_out^T + b_out ---------------------
__global__ __launch_bounds__(128) void feats_kernel(
    const float* __restrict__ h, const float* __restrict__ Wout,
    const float* __restrict__ bout, float* __restrict__ feats)
{
    __shared__ __align__(16) float hs[4][2 * HH];
    int m0 = blockIdx.x * 4;
    int tid = threadIdx.x;
    for (int i = tid * 4; i < 4 * 2 * HH; i += 128 * 4)
        *reinterpret_cast<float4*>(&hs[0][i]) =
            *reinterpret_cast<const float4*>(&h[(size_t)m0 * 2 * HH + i]);
    __syncthreads();
    int r = tid >> 5, tag = tid & 31;
    const float* w = Wout + (size_t)tag * (2 * HH);
    float acc = 0.0f;
    #pragma unroll 4
    for (int k = 0; k < 2 * HH; k += 4) {
        float4 wv = *reinterpret_cast<const float4*>(&w[k]);
        float4 hv = *reinterpret_cast<const float4*>(&hs[r][k]);
        acc += wv.x * hv.x + wv.y * hv.y + wv.z * hv.z + wv.w * hv.w;
    }
    feats[(size_t)(m0 + r) * KK + tag] = acc + bout[tag];
}

// ---------------- Viterbi: one block (32 threads) per batch row -----------------
__global__ __launch_bounds__(32) void viterbi_kernel(
    const float* __restrict__ feats, const float* __restrict__ trans,
    const float* __restrict__ startt, const float* __restrict__ stopt,
    float* __restrict__ out, int out_size)
{
    int b = blockIdx.x;
    int j = threadIdx.x;
    __shared__ unsigned char bp[TT - 1][KK];
    __shared__ int path[TT];

    float tr[KK];
    #pragma unroll
    for (int k = 0; k < KK; k++) tr[k] = trans[j * KK + k];

    float dp = startt[j] + feats[(size_t)b * KK + j];
    for (int t = 1; t < TT; t++) {
        float best = -INFINITY;
        int arg = 0;
        #pragma unroll
        for (int k = 0; k < KK; k++) {
            float v = tr[k] + __shfl_sync(0xffffffffu, dp, k);
            if (v > best) { best = v; arg = k; }        // first-index argmax tie-break
        }
        bp[t - 1][j] = (unsigned char)arg;
        dp = best + feats[((size_t)t * BB + b) * KK + j];
    }
    dp += stopt[j];

    // warp argmax with first-index tie-break
    float bv = dp; int bi = j;
    #pragma unroll
    for (int off = 16; off; off >>= 1) {
        float ov = __shfl_down_sync(0xffffffffu, bv, off);
        int   oi = __shfl_down_sync(0xffffffffu, bi, off);
        if (ov > bv || (ov == bv && oi < bi)) { bv = ov; bi = oi; }
    }
    bv = __shfl_sync(0xffffffffu, bv, 0);
    bi = __shfl_sync(0xffffffffu, bi, 0);

    if (j == 0) {
        path[TT - 1] = bi;
        int tag = bi;
        for (int t = TT - 2; t >= 0; t--) {
            tag = bp[t][tag];
            path[t] = tag;
        }
    }
    __syncwarp();

    int pathsOff = out_size - TT * BB;
    if (pathsOff >= (int)BB) {
        if (j == 0) out[b] = bv;                         // scores first
    } else if (pathsOff < 0) {
        if (j == 0 && b < out_size) out[b] = bv;         // scores-only fallback
        return;
    }
    for (int t = j; t < TT; t += 32)
        out[pathsOff + t * BB + b] = (float)path[t];
}

// ---------------- launch ---------------------------------------------------------
extern "C" void kernel_launch(void* const* d_in, const int* in_sizes, int n_in,
                              void* d_out, int out_size) {
    const int*   sent    = (const int*)d_in[0];
    const float* emb     = (const float*)d_in[1];
    const float* wih_l0f = (const float*)d_in[2];
    const float* whh_l0f = (const float*)d_in[3];
    const float* bih_l0f = (const float*)d_in[4];
    const float* bhh_l0f = (const float*)d_in[5];
    const float* wih_l0r = (const float*)d_in[6];
    const float* whh_l0r = (const float*)d_in[7];
    const float* bih_l0r = (const float*)d_in[8];
    const float* bhh_l0r = (const float*)d_in[9];
    const float* wih_l1f = (const float*)d_in[10];
    const float* whh_l1f = (const float*)d_in[11];
    const float* bih_l1f = (const float*)d_in[12];
    const float* bhh_l1f = (const float*)d_in[13];
    const float* wih_l1r = (const float*)d_in[14];
    const float* whh_l1r = (const float*)d_in[15];
    const float* bih_l1r = (const float*)d_in[16];
    const float* bhh_l1r = (const float*)d_in[17];
    const float* W_out   = (const float*)d_in[18];
    const float* b_out   = (const float*)d_in[19];
    const float* transit = (const float*)d_in[20];
    const float* start_t = (const float*)d_in[21];
    const float* stop_t  = (const float*)d_in[22];

    float *x0, *xpf, *xpr, *hbuf, *feats, *hstate;
    unsigned* bar;
    cudaGetSymbolAddress((void**)&x0,     g_x0);
    cudaGetSymbolAddress((void**)&xpf,    g_xpf);
    cudaGetSymbolAddress((void**)&xpr,    g_xpr);
    cudaGetSymbolAddress((void**)&hbuf,   g_hbuf);
    cudaGetSymbolAddress((void**)&feats,  g_feats);
    cudaGetSymbolAddress((void**)&hstate, g_hstate);
    cudaGetSymbolAddress((void**)&bar,    g_bar);

    cudaFuncSetAttribute(lstm_layer_kernel,
                         cudaFuncAttributeMaxDynamicSharedMemorySize, LSTM_SMEM);

    // 1) embedding
    embed_kernel<<<(TT * BB * (EE / 4) + 255) / 256, 256>>>(sent, emb, x0);

    dim3 gemm_grid(G4H / 128, MROWS / 128);  // (16, 128)

    // 2) layer 0 input projections
    sgemm_nt_bias<<<gemm_grid, 256>>>(x0, wih_l0f, bih_l0f, bhh_l0f, xpf, MROWS, G4H, EE);
    sgemm_nt_bias<<<gemm_grid, 256>>>(x0, wih_l0r, bih_l0r, bhh_l0r, xpr, MROWS, G4H, EE);

    // 3) layer 0 recurrence
    cudaMemsetAsync(hstate, 0, sizeof(float) * 2 * 2 * BB * HH);
    cudaMemsetAsync(bar, 0, sizeof(unsigned) * 2);
    lstm_layer_kernel<<<128, 256, LSTM_SMEM>>>(xpf, xpr, whh_l0f, whh_l0r, hbuf, hstate, bar);

    // 4) layer 1 input projections (input = hbuf, K = 2H)
    sgemm_nt_bias<<<gemm_grid, 256>>>(hbuf, wih_l1f, bih_l1f, bhh_l1f, xpf, MROWS, G4H, 2 * HH);
    sgemm_nt_bias<<<gemm_grid, 256>>>(hbuf, wih_l1r, bih_l1r, bhh_l1r, xpr, MROWS, G4H, 2 * HH);

    // 5) layer 1 recurrence (overwrites hbuf)
    cudaMemsetAsync(hstate, 0, sizeof(float) * 2 * 2 * BB * HH);
    cudaMemsetAsync(bar, 0, sizeof(unsigned) * 2);
    lstm_layer_kernel<<<128, 256, LSTM_SMEM>>>(xpf, xpr, whh_l1f, whh_l1r, hbuf, hstate, bar);

    // 6) emissions
    feats_kernel<<<MROWS / 4, 128>>>(hbuf, W_out, b_out, feats);

    // 7) Viterbi decode + output write
    viterbi_kernel<<<BB, 32>>>(feats, transit, start_t, stop_t, (float*)d_out, out_size);
}

// round 2
// speedup vs baseline: 1.0398x; 1.0398x over previous
#include <cuda_runtime.h>
#include <cstdint>
#include <math.h>

#define TT 256
#define BB 64
#define EE 256
#define HH 512
#define KK 32
#define G4H 2048
#define MROWS (TT*BB)          // 16384
#define WPAD 516               // padded smem row stride (floats) for LSTM kernel

// ---------------- scratch (static device allocations; no cudaMalloc anywhere) ----
__device__ float    g_x0[TT*BB*EE];          // embedded input      (T,B,E)
__device__ float    g_xpf[TT*BB*G4H];        // input proj fwd      (T,B,4H)
__device__ float    g_xpr[TT*BB*G4H];        // input proj rev      (T,B,4H)
__device__ float    g_hbuf[TT*BB*2*HH];      // layer output        (T,B,2H)
__device__ float    g_feats[TT*BB*KK];       // emissions           (T,B,K)
__device__ float    g_hstate[2*2*BB*HH];     // [buf][dir][B][H] double-buffered h
__device__ unsigned g_bar[2];                // per-direction barrier counters

// ---------------- small helpers --------------------------------------------------
__device__ __forceinline__ void ff2(unsigned long long &acc, unsigned long long a,
                                    unsigned long long b) {
    asm volatile("fma.rn.f32x2 %0, %1, %2, %0;" : "+l"(acc) : "l"(a), "l"(b));
}
__device__ __forceinline__ float hsum2(unsigned long long a) {
    float lo, hi;
    asm("mov.b64 {%0,%1}, %2;" : "=f"(lo), "=f"(hi) : "l"(a));
    return lo + hi;
}
__device__ __forceinline__ unsigned long long dup2(float x) {
    unsigned long long r;
    asm("mov.b64 %0, {%1,%1};" : "=l"(r) : "f"(x));
    return r;
}
__device__ __forceinline__ void unpk(unsigned long long a, float& lo, float& hi) {
    asm("mov.b64 {%0,%1}, %2;" : "=f"(lo), "=f"(hi) : "l"(a));
}
__device__ __forceinline__ float sigm(float x) { return 1.0f / (1.0f + expf(-x)); }

// ---------------- embedding gather ----------------------------------------------
__global__ void embed_kernel(const int* __restrict__ sent, const float* __restrict__ emb,
                             float* __restrict__ x0) {
    int i = blockIdx.x * blockDim.x + threadIdx.x;      // over T*B*(E/4)
    int total = TT * BB * (EE / 4);
    if (i >= total) return;
    int tb = i >> 6;          // E/4 = 64
    int e4 = i & 63;
    int v = sent[tb];
    reinterpret_cast<float4*>(x0)[i] =
        reinterpret_cast<const float4*>(emb + (size_t)v * EE)[e4];
}

// ---------------- f32x2 SGEMM: C(M,N) = A(M,K) @ W(N,K)^T + b1(N) + b2(N) --------
// 128x128 block tile, BK=8, 256 threads, 8x8 per-thread micro-tile computed as
// 4 m-pairs x 8 n via fma.rn.f32x2. B is stored in smem pre-duplicated
// ((b,b) pairs) so each ff2 serves two output rows. Thread chunks in Bd are
// padded to 80B stride to keep LDS conflicts at 2-way.
#define ROWU 160   // ulls per Bd k-row: 16 chunks * (8 data + 2 pad)

__global__ __launch_bounds__(256) void sgemm_nt_bias(
    const float* __restrict__ A, const float* __restrict__ W,
    const float* __restrict__ b1, const float* __restrict__ b2,
    float* __restrict__ C, int M, int N, int K)
{
    __shared__ __align__(16) float As[8][128];
    __shared__ __align__(16) unsigned long long Bd[8 * ROWU];
    const int tid  = threadIdx.x;
    const int bn   = blockIdx.x * 128;
    const int bm   = blockIdx.y * 128;
    const int lrow = tid >> 1;
    const int lkq  = (tid & 1) * 4;
    const float* Ap = A + (size_t)(bm + lrow) * K + lkq;
    const float* Wp = W + (size_t)(bn + lrow) * K + lkq;
    const int tx = tid & 15;
    const int ty = tid >> 4;
    const int bpos = (lrow >> 3) * 10 + (lrow & 7);  // padded chunk position

    unsigned long long acc[4][8];
    #pragma unroll
    for (int i = 0; i < 4; i++)
        #pragma unroll
        for (int j = 0; j < 8; j++) acc[i][j] = 0ULL;

    for (int kt = 0; kt < K; kt += 8) {
        float4 a = *reinterpret_cast<const float4*>(Ap + kt);
        float4 w = *reinterpret_cast<const float4*>(Wp + kt);
        As[lkq + 0][lrow] = a.x; As[lkq + 1][lrow] = a.y;
        As[lkq + 2][lrow] = a.z; As[lkq + 3][lrow] = a.w;
        Bd[(lkq + 0) * ROWU + bpos] = dup2(w.x);
        Bd[(lkq + 1) * ROWU + bpos] = dup2(w.y);
        Bd[(lkq + 2) * ROWU + bpos] = dup2(w.z);
        Bd[(lkq + 3) * ROWU + bpos] = dup2(w.w);
        __syncthreads();
        #pragma unroll
        for (int k = 0; k < 8; k++) {
            ulonglong2 a01 = *reinterpret_cast<const ulonglong2*>(&As[k][ty * 8]);
            ulonglong2 a23 = *reinterpret_cast<const ulonglong2*>(&As[k][ty * 8 + 4]);
            const unsigned long long* bp = &Bd[k * ROWU + tx * 10];
            ulonglong2 b01 = *reinterpret_cast<const ulonglong2*>(bp + 0);
            ulonglong2 b23 = *reinterpret_cast<const ulonglong2*>(bp + 2);
            ulonglong2 b45 = *reinterpret_cast<const ulonglong2*>(bp + 4);
            ulonglong2 b67 = *reinterpret_cast<const ulonglong2*>(bp + 6);
            unsigned long long av[4] = {a01.x, a01.y, a23.x, a23.y};
            unsigned long long bv[8] = {b01.x, b01.y, b23.x, b23.y,
                                        b45.x, b45.y, b67.x, b67.y};
            #pragma unroll
            for (int ip = 0; ip < 4; ip++)
                #pragma unroll
                for (int j = 0; j < 8; j++)
                    ff2(acc[ip][j], av[ip], bv[j]);
        }
        __syncthreads();
    }

    // epilogue: add biases, vector stores
    const int n0 = bn + tx * 8;
    float bsum[8];
    #pragma unroll
    for (int j = 0; j < 8; j++) bsum[j] = b1[n0 + j] + b2[n0 + j];
    #pragma unroll
    for (int ip = 0; ip < 4; ip++) {
        float lo[8], hi[8];
        #pragma unroll
        for (int j = 0; j < 8; j++) unpk(acc[ip][j], lo[j], hi[j]);
        size_t r0 = (size_t)(bm + ty * 8 + 2 * ip) * N + n0;
        size_t r1 = r0 + N;
        *reinterpret_cast<float4*>(&C[r0]) =
            make_float4(lo[0] + bsum[0], lo[1] + bsum[1], lo[2] + bsum[2], lo[3] + bsum[3]);
        *reinterpret_cast<float4*>(&C[r0 + 4]) =
            make_float4(lo[4] + bsum[4], lo[5] + bsum[5], lo[6] + bsum[6], lo[7] + bsum[7]);
        *reinterpret_cast<float4*>(&C[r1]) =
            make_float4(hi[0] + bsum[0], hi[1] + bsum[1], hi[2] + bsum[2], hi[3] + bsum[3]);
        *reinterpret_cast<float4*>(&C[r1 + 4]) =
            make_float4(hi[4] + bsum[4], hi[5] + bsum[5], hi[6] + bsum[6], hi[7] + bsum[7]);
    }
}

// ---------------- persistent bidirectional LSTM layer ---------------------------
// Grid: 128 blocks (64/dir), 256 threads. Block `sub` owns 8 h-columns (all batch).
// W_hh slice (32 rows x 512) cached in smem for the whole sequence.
// h state double-buffered in global; per-direction software barrier each step.
#define LSTM_SMEM ((32 * WPAD + 64 * WPAD) * 4)

__global__ __launch_bounds__(256) void lstm_layer_kernel(
    const float* __restrict__ xpf, const float* __restrict__ xpr,
    const float* __restrict__ whf, const float* __restrict__ whr,
    float* __restrict__ hout, float* hstate, unsigned* bar)
{
    extern __shared__ __align__(16) float sm[];
    float* Wsm = sm;                 // [32][WPAD]
    float* Hsm = sm + 32 * WPAD;     // [64][WPAD]
    const int tid = threadIdx.x;
    const int dir = blockIdx.x >> 6;
    const int sub = blockIdx.x & 63;
    const int j0  = sub * 8;
    const float* W  = dir ? whr : whf;
    const float* xp = dir ? xpr : xpf;

    // cache W_hh slice once (rows {gate*512 + j0 + jl})
    for (int i = tid; i < 32 * 128; i += 256) {
        int r = i >> 7;
        int c = (i & 127) * 4;
        int gate = r >> 3, jl2 = r & 7;
        *reinterpret_cast<float4*>(&Wsm[r * WPAD + c]) =
            *reinterpret_cast<const float4*>(&W[(size_t)(gate * 512 + j0 + jl2) * HH + c]);
    }

    const int jl = tid & 7;
    const int b0 = tid >> 3;       // 0..31
    const int b1 = b0 + 32;
    const int j  = j0 + jl;
    float c0 = 0.0f, c1 = 0.0f;

    const ulonglong2* wip = reinterpret_cast<const ulonglong2*>(&Wsm[(0 * 8 + jl) * WPAD]);
    const ulonglong2* wfp = reinterpret_cast<const ulonglong2*>(&Wsm[(1 * 8 + jl) * WPAD]);
    const ulonglong2* wgp = reinterpret_cast<const ulonglong2*>(&Wsm[(2 * 8 + jl) * WPAD]);
    const ulonglong2* wop = reinterpret_cast<const ulonglong2*>(&Wsm[(3 * 8 + jl) * WPAD]);
    const ulonglong2* h0p = reinterpret_cast<const ulonglong2*>(&Hsm[b0 * WPAD]);
    const ulonglong2* h1p = reinterpret_cast<const ulonglong2*>(&Hsm[b1 * WPAD]);

    for (int s = 0; s < TT; s++) {
        const int rb = s & 1, wb = rb ^ 1;
        const int tt = dir ? (TT - 1 - s) : s;
        const float* xpt = xp + (size_t)tt * BB * G4H;

        // prefetch the 8 input-projection gate values (DRAM) at step start
        float xi0 = xpt[b0 * G4H + 0 * HH + j];
        float xf0 = xpt[b0 * G4H + 1 * HH + j];
        float xg0 = xpt[b0 * G4H + 2 * HH + j];
        float xo0 = xpt[b0 * G4H + 3 * HH + j];
        float xi1 = xpt[b1 * G4H + 0 * HH + j];
        float xf1 = xpt[b1 * G4H + 1 * HH + j];
        float xg1 = xpt[b1 * G4H + 2 * HH + j];
        float xo1 = xpt[b1 * G4H + 3 * HH + j];

        const float* hsrc = hstate + (size_t)(rb * 2 + dir) * (BB * HH);
        // broadcast previous h into smem (padded rows)
        for (int i = tid; i < BB * 128; i += 256) {
            int b = i >> 7;
            int c = (i & 127) * 4;
            *reinterpret_cast<float4*>(&Hsm[b * WPAD + c]) =
                *reinterpret_cast<const float4*>(&hsrc[b * HH + c]);
        }
        __syncthreads();

        unsigned long long aI0 = 0, aF0 = 0, aG0 = 0, aO0 = 0;
        unsigned long long aI1 = 0, aF1 = 0, aG1 = 0, aO1 = 0;
        #pragma unroll 4
        for (int k = 0; k < 128; k++) {
            ulonglong2 h0 = h0p[k], h1 = h1p[k];
            ulonglong2 wi = wip[k], wf = wfp[k], wg = wgp[k], wo = wop[k];
            ff2(aI0, wi.x, h0.x); ff2(aI0, wi.y, h0.y);
            ff2(aF0, wf.x, h0.x); ff2(aF0, wf.y, h0.y);
            ff2(aG0, wg.x, h0.x); ff2(aG0, wg.y, h0.y);
            ff2(aO0, wo.x, h0.x); ff2(aO0, wo.y, h0.y);
            ff2(aI1, wi.x, h1.x); ff2(aI1, wi.y, h1.y);
            ff2(aF1, wf.x, h1.x); ff2(aF1, wf.y, h1.y);
            ff2(aG1, wg.x, h1.x); ff2(aG1, wg.y, h1.y);
            ff2(aO1, wo.x, h1.x); ff2(aO1, wo.y, h1.y);
        }

        float gi0 = xi0 + hsum2(aI0);
        float gf0 = xf0 + hsum2(aF0);
        float gg0 = xg0 + hsum2(aG0);
        float go0 = xo0 + hsum2(aO0);
        float gi1 = xi1 + hsum2(aI1);
        float gf1 = xf1 + hsum2(aF1);
        float gg1 = xg1 + hsum2(aG1);
        float go1 = xo1 + hsum2(aO1);

        c0 = sigm(gf0) * c0 + sigm(gi0) * tanhf(gg0);
        float h0v = sigm(go0) * tanhf(c0);
        c1 = sigm(gf1) * c1 + sigm(gi1) * tanhf(gg1);
        float h1v = sigm(go1) * tanhf(c1);

        float* hdst = hstate + (size_t)(wb * 2 + dir) * (BB * HH);
        hdst[b0 * HH + j] = h0v;
        hdst[b1 * HH + j] = h1v;
        float* op = hout + (size_t)tt * BB * (2 * HH) + (size_t)dir * HH;
        op[(size_t)b0 * (2 * HH) + j] = h0v;
        op[(size_t)b1 * (2 * HH) + j] = h1v;

        __syncthreads();
        if (s + 1 < TT) {
            if (tid == 0) {
                __threadfence();
                atomicAdd(&bar[dir], 1u);
                unsigned target = 64u * (unsigned)(s + 1);
                volatile unsigned* p = bar + dir;
                while (*p < target) __nanosleep(64);
                __threadfence();
            }
            __syncthreads();
        }
    }
}

// ---------------- emissions: feats = hbuf @ W_out^T + b_out ---------------------
__global__ __launch_bounds__(128) void feats_kernel(
    const float* __restrict__ h, const float* __restrict__ Wout,
    const float* __restrict__ bout, float* __restrict__ feats)
{
    __shared__ __align__(16) float hs[4][2 * HH];
    int m0 = blockIdx.x * 4;
    int tid = threadIdx.x;
    for (int i = tid * 4; i < 4 * 2 * HH; i += 128 * 4)
        *reinterpret_cast<float4*>(&hs[0][i]) =
            *reinterpret_cast<const float4*>(&h[(size_t)m0 * 2 * HH + i]);
    __syncthreads();
    int r = tid >> 5, tag = tid & 31;
    const float* w = Wout + (size_t)tag * (2 * HH);
    float acc = 0.0f;
    #pragma unroll 4
    for (int k = 0; k < 2 * HH; k += 4) {
        float4 wv = *reinterpret_cast<const float4*>(&w[k]);
        float4 hv = *reinterpret_cast<const float4*>(&hs[r][k]);
        acc += wv.x * hv.x + wv.y * hv.y + wv.z * hv.z + wv.w * hv.w;
    }
    feats[(size_t)(m0 + r) * KK + tag] = acc + bout[tag];
}

// ---------------- Viterbi: one block (32 threads) per batch row -----------------
__global__ __launch_bounds__(32) void viterbi_kernel(
    const float* __restrict__ feats, const float* __restrict__ trans,
    const float* __restrict__ startt, const float* __restrict__ stopt,
    float* __restrict__ out, int out_size)
{
    int b = blockIdx.x;
    int j = threadIdx.x;
    __shared__ unsigned char bp[TT - 1][KK];
    __shared__ int path[TT];

    float tr[KK];
    #pragma unroll
    for (int k = 0; k < KK; k++) tr[k] = trans[j * KK + k];

    float dp = startt[j] + feats[(size_t)b * KK + j];
    for (int t = 1; t < TT; t++) {
        float best = -INFINITY;
        int arg = 0;
        #pragma unroll
        for (int k = 0; k < KK; k++) {
            float v = tr[k] + __shfl_sync(0xffffffffu, dp, k);
            if (v > best) { best = v; arg = k; }        // first-index argmax tie-break
        }
        bp[t - 1][j] = (unsigned char)arg;
        dp = best + feats[((size_t)t * BB + b) * KK + j];
    }
    dp += stopt[j];

    // warp argmax with first-index tie-break
    float bv = dp; int bi = j;
    #pragma unroll
    for (int off = 16; off; off >>= 1) {
        float ov = __shfl_down_sync(0xffffffffu, bv, off);
        int   oi = __shfl_down_sync(0xffffffffu, bi, off);
        if (ov > bv || (ov == bv && oi < bi)) { bv = ov; bi = oi; }
    }
    bv = __shfl_sync(0xffffffffu, bv, 0);
    bi = __shfl_sync(0xffffffffu, bi, 0);

    if (j == 0) {
        path[TT - 1] = bi;
        int tag = bi;
        for (int t = TT - 2; t >= 0; t--) {
            tag = bp[t][tag];
            path[t] = tag;
        }
    }
    __syncwarp();

    int pathsOff = out_size - TT * BB;
    if (pathsOff >= (int)BB) {
        if (j == 0) out[b] = bv;                         // scores first
    } else if (pathsOff < 0) {
        if (j == 0 && b < out_size) out[b] = bv;         // scores-only fallback
        return;
    }
    for (int t = j; t < TT; t += 32)
        out[pathsOff + t * BB + b] = (float)path[t];
}

// ---------------- launch ---------------------------------------------------------
extern "C" void kernel_launch(void* const* d_in, const int* in_sizes, int n_in,
                              void* d_out, int out_size) {
    const int*   sent    = (const int*)d_in[0];
    const float* emb     = (const float*)d_in[1];
    const float* wih_l0f = (const float*)d_in[2];
    const float* whh_l0f = (const float*)d_in[3];
    const float* bih_l0f = (const float*)d_in[4];
    const float* bhh_l0f = (const float*)d_in[5];
    const float* wih_l0r = (const float*)d_in[6];
    const float* whh_l0r = (const float*)d_in[7];
    const float* bih_l0r = (const float*)d_in[8];
    const float* bhh_l0r = (const float*)d_in[9];
    const float* wih_l1f = (const float*)d_in[10];
    const float* whh_l1f = (const float*)d_in[11];
    const float* bih_l1f = (const float*)d_in[12];
    const float* bhh_l1f = (const float*)d_in[13];
    const float* wih_l1r = (const float*)d_in[14];
    const float* whh_l1r = (const float*)d_in[15];
    const float* bih_l1r = (const float*)d_in[16];
    const float* bhh_l1r = (const float*)d_in[17];
    const float* W_out   = (const float*)d_in[18];
    const float* b_out   = (const float*)d_in[19];
    const float* transit = (const float*)d_in[20];
    const float* start_t = (const float*)d_in[21];
    const float* stop_t  = (const float*)d_in[22];

    float *x0, *xpf, *xpr, *hbuf, *feats, *hstate;
    unsigned* bar;
    cudaGetSymbolAddress((void**)&x0,     g_x0);
    cudaGetSymbolAddress((void**)&xpf,    g_xpf);
    cudaGetSymbolAddress((void**)&xpr,    g_xpr);
    cudaGetSymbolAddress((void**)&hbuf,   g_hbuf);
    cudaGetSymbolAddress((void**)&feats,  g_feats);
    cudaGetSymbolAddress((void**)&hstate, g_hstate);
    cudaGetSymbolAddress((void**)&bar,    g_bar);

    cudaFuncSetAttribute(lstm_layer_kernel,
                         cudaFuncAttributeMaxDynamicSharedMemorySize, LSTM_SMEM);

    // 1) embedding
    embed_kernel<<<(TT * BB * (EE / 4) + 255) / 256, 256>>>(sent, emb, x0);

    dim3 gemm_grid(G4H / 128, MROWS / 128);  // (16, 128)

    // 2) layer 0 input projections
    sgemm_nt_bias<<<gemm_grid, 256>>>(x0, wih_l0f, bih_l0f, bhh_l0f, xpf, MROWS, G4H, EE);
    sgemm_nt_bias<<<gemm_grid, 256>>>(x0, wih_l0r, bih_l0r, bhh_l0r, xpr, MROWS, G4H, EE);

    // 3) layer 0 recurrence
    cudaMemsetAsync(hstate, 0, sizeof(float) * 2 * 2 * BB * HH);
    cudaMemsetAsync(bar, 0, sizeof(unsigned) * 2);
    lstm_layer_kernel<<<128, 256, LSTM_SMEM>>>(xpf, xpr, whh_l0f, whh_l0r, hbuf, hstate, bar);

    // 4) layer 1 input projections (input = hbuf, K = 2H)
    sgemm_nt_bias<<<gemm_grid, 256>>>(hbuf, wih_l1f, bih_l1f, bhh_l1f, xpf, MROWS, G4H, 2 * HH);
    sgemm_nt_bias<<<gemm_grid, 256>>>(hbuf, wih_l1r, bih_l1r, bhh_l1r, xpr, MROWS, G4H, 2 * HH);

    // 5) layer 1 recurrence (overwrites hbuf)
    cudaMemsetAsync(hstate, 0, sizeof(float) * 2 * 2 * BB * HH);
    cudaMemsetAsync(bar, 0, sizeof(unsigned) * 2);
    lstm_layer_kernel<<<128, 256, LSTM_SMEM>>>(xpf, xpr, whh_l1f, whh_l1r, hbuf, hstate, bar);

    // 6) emissions
    feats_kernel<<<MROWS / 4, 128>>>(hbuf, W_out, b_out, feats);

    // 7) Viterbi decode + output write
    viterbi_kernel<<<BB, 32>>>(feats, transit, start_t, stop_t, (float*)d_out, out_size);
}

// round 4
// speedup vs baseline: 1.1802x; 1.1351x over previous
#include <cuda_runtime.h>
#include <cstdint>
#include <math.h>

#define TT 256
#define BB 64
#define EE 256
#define HH 512
#define KK 32
#define G4H 2048
#define MROWS (TT*BB)          // 16384
#define WPAD 516               // padded smem row stride (floats) for LSTM kernel

// ---------------- scratch (static device allocations; no cudaMalloc) ------------
__device__ float    g_xpf[MROWS*G4H];        // input proj fwd      (T,B,4H)
__device__ float    g_xpr[MROWS*G4H];        // input proj rev      (T,B,4H)
__device__ float    g_hbuf[MROWS*2*HH];      // layer output        (T,B,2H)
__device__ float    g_feats[MROWS*KK];       // emissions           (T,B,K)
__device__ float    g_hstate[2*2*BB*HH];     // [buf][dir][B][H] double-buffered h
__device__ unsigned g_bar[2];                // per-direction barrier counters
// tf32 hi/lo splits (stored as fp32 bit patterns, already tf32-rounded)
__device__ __align__(16) float g_as[2][MROWS*EE];      // embedded x splits
__device__ __align__(16) float g_hs[2][MROWS*2*HH];    // hbuf splits
__device__ __align__(16) float g_w0f[2][G4H*EE];
__device__ __align__(16) float g_w0r[2][G4H*EE];
__device__ __align__(16) float g_w1f[2][G4H*2*HH];
__device__ __align__(16) float g_w1r[2][G4H*2*HH];

// ---------------- small helpers --------------------------------------------------
__device__ __forceinline__ void ff2(unsigned long long &acc, unsigned long long a,
                                    unsigned long long b) {
    asm volatile("fma.rn.f32x2 %0, %1, %2, %0;" : "+l"(acc) : "l"(a), "l"(b));
}
__device__ __forceinline__ float hsum2(unsigned long long a) {
    float lo, hi;
    asm("mov.b64 {%0,%1}, %2;" : "=f"(lo), "=f"(hi) : "l"(a));
    return lo + hi;
}
__device__ __forceinline__ float sigm(float x) { return 1.0f / (1.0f + expf(-x)); }

__device__ __forceinline__ void split_tf32(float x, float& hi, float& lo) {
    uint32_t h;
    asm("cvt.rna.tf32.f32 %0, %1;" : "=r"(h) : "f"(x));
    hi = __uint_as_float(h);
    float r = x - hi;
    uint32_t l;
    asm("cvt.rna.tf32.f32 %0, %1;" : "=r"(l) : "f"(r));
    lo = __uint_as_float(l);
}

__device__ __forceinline__ uint32_t smem_u32(const void* p) {
    uint32_t a;
    asm("{ .reg .u64 t; cvta.to.shared.u64 t, %1; cvt.u32.u64 %0, t; }"
        : "=r"(a) : "l"(p));
    return a;
}
__device__ __forceinline__ void cp16(uint32_t dst, const void* src) {
    asm volatile("cp.async.cg.shared.global [%0], [%1], 16;"
                 :: "r"(dst), "l"(src) : "memory");
}
__device__ __forceinline__ void cp_commit() {
    asm volatile("cp.async.commit_group;" ::: "memory");
}
__device__ __forceinline__ void cp_wait1() {
    asm volatile("cp.async.wait_group 1;" ::: "memory");
}
__device__ __forceinline__ void cp_wait0() {
    asm volatile("cp.async.wait_group 0;" ::: "memory");
}
__device__ __forceinline__ void mma_tf32(float* d, const uint32_t* a,
                                         uint32_t b0, uint32_t b1) {
    asm volatile(
        "mma.sync.aligned.m16n8k8.row.col.f32.tf32.tf32.f32 "
        "{%0,%1,%2,%3}, {%4,%5,%6,%7}, {%8,%9}, {%0,%1,%2,%3};"
        : "+f"(d[0]), "+f"(d[1]), "+f"(d[2]), "+f"(d[3])
        : "r"(a[0]), "r"(a[1]), "r"(a[2]), "r"(a[3]), "r"(b0), "r"(b1));
}

// ---------------- tf32 split of an fp32 array (float4 granularity) --------------
__global__ void split2_kernel(const float* __restrict__ in, float* __restrict__ oh,
                              float* __restrict__ ol, int n4) {
    int i = blockIdx.x * blockDim.x + threadIdx.x;
    if (i >= n4) return;
    float4 a = reinterpret_cast<const float4*>(in)[i];
    float4 h, l;
    split_tf32(a.x, h.x, l.x);
    split_tf32(a.y, h.y, l.y);
    split_tf32(a.z, h.z, l.z);
    split_tf32(a.w, h.w, l.w);
    reinterpret_cast<float4*>(oh)[i] = h;
    reinterpret_cast<float4*>(ol)[i] = l;
}

// ---------------- embedding gather fused with tf32 split ------------------------
__global__ void embed_split_kernel(const int* __restrict__ sent,
                                   const float* __restrict__ emb,
                                   float* __restrict__ oh, float* __restrict__ ol) {
    int i = blockIdx.x * blockDim.x + threadIdx.x;      // over T*B*(E/4)
    int total = TT * BB * (EE / 4);
    if (i >= total) return;
    int tb = i >> 6;
    int e4 = i & 63;
    int v = sent[tb];
    float4 a = reinterpret_cast<const float4*>(emb + (size_t)v * EE)[e4];
    float4 h, l;
    split_tf32(a.x, h.x, l.x);
    split_tf32(a.y, h.y, l.y);
    split_tf32(a.z, h.z, l.z);
    split_tf32(a.w, h.w, l.w);
    reinterpret_cast<float4*>(oh)[i] = h;
    reinterpret_cast<float4*>(ol)[i] = l;
}

// ---------------- 3xTF32 mma.sync GEMM ------------------------------------------
// C(M,2048) = A(M,K) @ W(2048,K)^T + bi1 + bi2, fp32-equivalent accuracy via
// terms hh + hl + lh. 128x128 CTA tile, BK=16, 8 warps (64x32 warp tiles),
// cp.async double buffering. Smem rows padded to 20 floats (conflict-free frags).
#define TPAD 20
#define TILE_F (128 * TPAD)          // floats per tile
#define STAGE_F (4 * TILE_F)         // Ah, Al, Wh, Wl
#define GEMM_SMEM (2 * STAGE_F * 4)  // bytes = 81920

__global__ __launch_bounds__(256) void tf32_gemm(
    const float* __restrict__ Ah, const float* __restrict__ Al,
    const float* __restrict__ Wh, const float* __restrict__ Wl,
    const float* __restrict__ bi1, const float* __restrict__ bi2,
    float* __restrict__ C, int K)
{
    extern __shared__ __align__(16) float smem[];
    const uint32_t sb = smem_u32(smem);
    const int tid = threadIdx.x, lane = tid & 31, wid = tid >> 5;
    const int wm = wid & 1, wn = wid >> 1;             // 2 x 4 warp grid
    const int bn = blockIdx.x * 128, bm = blockIdx.y * 128;
    const int nch = K >> 4;

    const int qr = lane >> 2;   // 0..7
    const int qc = lane & 3;    // 0..3

    float acc[4][4][4];
    #pragma unroll
    for (int mi = 0; mi < 4; mi++)
        #pragma unroll
        for (int ni = 0; ni < 4; ni++)
            #pragma unroll
            for (int q = 0; q < 4; q++) acc[mi][ni][q] = 0.0f;

    // cp.async issue for chunk c into stage st: 2048 16B segments, 8 per thread
    auto issue = [&](int c, int st) {
        #pragma unroll
        for (int i = 0; i < 8; i++) {
            int s = tid + i * 256;
            int tile = s >> 9;            // 0:Ah 1:Al 2:Wh 3:Wl
            int r = (s >> 2) & 127;
            int sub = s & 3;
            const float* g;
            if (tile == 0)      g = Ah + (size_t)(bm + r) * K + c * 16 + sub * 4;
            else if (tile == 1) g = Al + (size_t)(bm + r) * K + c * 16 + sub * 4;
            else if (tile == 2) g = Wh + (size_t)(bn + r) * K + c * 16 + sub * 4;
            else                g = Wl + (size_t)(bn + r) * K + c * 16 + sub * 4;
            uint32_t d = sb + (uint32_t)(st * STAGE_F + tile * TILE_F + r * TPAD + sub * 4) * 4;
            cp16(d, g);
        }
        cp_commit();
    };

    issue(0, 0);

    for (int c = 0; c < nch; c++) {
        const int st = c & 1;
        if (c + 1 < nch) { issue(c + 1, st ^ 1); cp_wait1(); }
        else cp_wait0();
        __syncthreads();

        const float* Ah_s = smem + st * STAGE_F;
        const float* Al_s = Ah_s + TILE_F;
        const float* Wh_s = Ah_s + 2 * TILE_F;
        const float* Wl_s = Ah_s + 3 * TILE_F;

        #pragma unroll
        for (int s8 = 0; s8 < 16; s8 += 8) {
            #pragma unroll
            for (int t = 0; t < 3; t++) {
                const float* At = (t == 2) ? Al_s : Ah_s;
                const float* Wt = (t == 1) ? Wl_s : Wh_s;
                uint32_t a[4][4];
                #pragma unroll
                for (int mi = 0; mi < 4; mi++) {
                    int m = wm * 64 + mi * 16 + qr;
                    const uint32_t* p =
                        reinterpret_cast<const uint32_t*>(At + m * TPAD + s8 + qc);
                    a[mi][0] = p[0];
                    a[mi][2] = p[4];
                    const uint32_t* p8 =
                        reinterpret_cast<const uint32_t*>(At + (m + 8) * TPAD + s8 + qc);
                    a[mi][1] = p8[0];
                    a[mi][3] = p8[4];
                }
                #pragma unroll
                for (int ni = 0; ni < 4; ni++) {
                    int n = wn * 32 + ni * 8 + qr;
                    const uint32_t* p =
                        reinterpret_cast<const uint32_t*>(Wt + n * TPAD + s8 + qc);
                    uint32_t b0 = p[0], b1 = p[4];
                    #pragma unroll
                    for (int mi = 0; mi < 4; mi++)
                        mma_tf32(acc[mi][ni], a[mi], b0, b1);
                }
            }
        }
        __syncthreads();
    }

    // epilogue: fused biases, float2 stores
    #pragma unroll
    for (int ni = 0; ni < 4; ni++) {
        int col = bn + wn * 32 + ni * 8 + 2 * qc;
        float2 s1 = *reinterpret_cast<const float2*>(bi1 + col);
        float2 s2 = *reinterpret_cast<const float2*>(bi2 + col);
        float bx = s1.x + s2.x, by = s1.y + s2.y;
        #pragma unroll
        for (int mi = 0; mi < 4; mi++) {
            int row = bm + wm * 64 + mi * 16 + qr;
            float2 v0 = make_float2(acc[mi][ni][0] + bx, acc[mi][ni][1] + by);
            float2 v1 = make_float2(acc[mi][ni][2] + bx, acc[mi][ni][3] + by);
            *reinterpret_cast<float2*>(&C[(size_t)row * G4H + col]) = v0;
            *reinterpret_cast<float2*>(&C[(size_t)(row + 8) * G4H + col]) = v1;
        }
    }
}

// ---------------- persistent bidirectional LSTM layer (unchanged) ---------------
#define LSTM_SMEM ((32 * WPAD + 64 * WPAD) * 4)

__global__ __launch_bounds__(256) void lstm_layer_kernel(
    const float* __restrict__ xpf, const float* __restrict__ xpr,
    const float* __restrict__ whf, const float* __restrict__ whr,
    float* __restrict__ hout, float* hstate, unsigned* bar)
{
    extern __shared__ __align__(16) float sm[];
    float* Wsm = sm;                 // [32][WPAD]
    float* Hsm = sm + 32 * WPAD;     // [64][WPAD]
    const int tid = threadIdx.x;
    const int dir = blockIdx.x >> 6;
    const int sub = blockIdx.x & 63;
    const int j0  = sub * 8;
    const float* W  = dir ? whr : whf;
    const float* xp = dir ? xpr : xpf;

    for (int i = tid; i < 32 * 128; i += 256) {
        int r = i >> 7;
        int c = (i & 127) * 4;
        int gate = r >> 3, jl2 = r & 7;
        *reinterpret_cast<float4*>(&Wsm[r * WPAD + c]) =
            *reinterpret_cast<const float4*>(&W[(size_t)(gate * 512 + j0 + jl2) * HH + c]);
    }

    const int jl = tid & 7;
    const int b0 = tid >> 3;
    const int b1 = b0 + 32;
    const int j  = j0 + jl;
    float c0 = 0.0f, c1 = 0.0f;

    const ulonglong2* wip = reinterpret_cast<const ulonglong2*>(&Wsm[(0 * 8 + jl) * WPAD]);
    const ulonglong2* wfp = reinterpret_cast<const ulonglong2*>(&Wsm[(1 * 8 + jl) * WPAD]);
    const ulonglong2* wgp = reinterpret_cast<const ulonglong2*>(&Wsm[(2 * 8 + jl) * WPAD]);
    const ulonglong2* wop = reinterpret_cast<const ulonglong2*>(&Wsm[(3 * 8 + jl) * WPAD]);
    const ulonglong2* h0p = reinterpret_cast<const ulonglong2*>(&Hsm[b0 * WPAD]);
    const ulonglong2* h1p = reinterpret_cast<const ulonglong2*>(&Hsm[b1 * WPAD]);

    for (int s = 0; s < TT; s++) {
        const int rb = s & 1, wb = rb ^ 1;
        const int tt = dir ? (TT - 1 - s) : s;
        const float* xpt = xp + (size_t)tt * BB * G4H;

        float xi0 = xpt[b0 * G4H + 0 * HH + j];
        float xf0 = xpt[b0 * G4H + 1 * HH + j];
        float xg0 = xpt[b0 * G4H + 2 * HH + j];
        float xo0 = xpt[b0 * G4H + 3 * HH + j];
        float xi1 = xpt[b1 * G4H + 0 * HH + j];
        float xf1 = xpt[b1 * G4H + 1 * HH + j];
        float xg1 = xpt[b1 * G4H + 2 * HH + j];
        float xo1 = xpt[b1 * G4H + 3 * HH + j];

        const float* hsrc = hstate + (size_t)(rb * 2 + dir) * (BB * HH);
        for (int i = tid; i < BB * 128; i += 256) {
            int b = i >> 7;
            int c = (i & 127) * 4;
            *reinterpret_cast<float4*>(&Hsm[b * WPAD + c]) =
                *reinterpret_cast<const float4*>(&hsrc[b * HH + c]);
        }
        __syncthreads();

        unsigned long long aI0 = 0, aF0 = 0, aG0 = 0, aO0 = 0;
        unsigned long long aI1 = 0, aF1 = 0, aG1 = 0, aO1 = 0;
        #pragma unroll 4
        for (int k = 0; k < 128; k++) {
            ulonglong2 h0 = h0p[k], h1 = h1p[k];
            ulonglong2 wi = wip[k], wf = wfp[k], wg = wgp[k], wo = wop[k];
            ff2(aI0, wi.x, h0.x); ff2(aI0, wi.y, h0.y);
            ff2(aF0, wf.x, h0.x); ff2(aF0, wf.y, h0.y);
            ff2(aG0, wg.x, h0.x); ff2(aG0, wg.y, h0.y);
            ff2(aO0, wo.x, h0.x); ff2(aO0, wo.y, h0.y);
            ff2(aI1, wi.x, h1.x); ff2(aI1, wi.y, h1.y);
            ff2(aF1, wf.x, h1.x); ff2(aF1, wf.y, h1.y);
            ff2(aG1, wg.x, h1.x); ff2(aG1, wg.y, h1.y);
            ff2(aO1, wo.x, h1.x); ff2(aO1, wo.y, h1.y);
        }

        float gi0 = xi0 + hsum2(aI0);
        float gf0 = xf0 + hsum2(aF0);
        float gg0 = xg0 + hsum2(aG0);
        float go0 = xo0 + hsum2(aO0);
        float gi1 = xi1 + hsum2(aI1);
        float gf1 = xf1 + hsum2(aF1);
        float gg1 = xg1 + hsum2(aG1);
        float go1 = xo1 + hsum2(aO1);

        c0 = sigm(gf0) * c0 + sigm(gi0) * tanhf(gg0);
        float h0v = sigm(go0) * tanhf(c0);
        c1 = sigm(gf1) * c1 + sigm(gi1) * tanhf(gg1);
        float h1v = sigm(go1) * tanhf(c1);

        float* hdst = hstate + (size_t)(wb * 2 + dir) * (BB * HH);
        hdst[b0 * HH + j] = h0v;
        hdst[b1 * HH + j] = h1v;
        float* op = hout + (size_t)tt * BB * (2 * HH) + (size_t)dir * HH;
        op[(size_t)b0 * (2 * HH) + j] = h0v;
        op[(size_t)b1 * (2 * HH) + j] = h1v;

        __syncthreads();
        if (s + 1 < TT) {
            if (tid == 0) {
                __threadfence();
                atomicAdd(&bar[dir], 1u);
                unsigned target = 64u * (unsigned)(s + 1);
                volatile unsigned* p = bar + dir;
                while (*p < target) __nanosleep(64);
                __threadfence();
            }
            __syncthreads();
        }
    }
}

// ---------------- emissions: feats = hbuf @ W_out^T + b_out ---------------------
__global__ __launch_bounds__(128) void feats_kernel(
    const float* __restrict__ h, const float* __restrict__ Wout,
    const float* __restrict__ bout, float* __restrict__ feats)
{
    __shared__ __align__(16) float hs[4][2 * HH];
    int m0 = blockIdx.x * 4;
    int tid = threadIdx.x;
    for (int i = tid * 4; i < 4 * 2 * HH; i += 128 * 4)
        *reinterpret_cast<float4*>(&hs[0][i]) =
            *reinterpret_cast<const float4*>(&h[(size_t)m0 * 2 * HH + i]);
    __syncthreads();
    int r = tid >> 5, tag = tid & 31;
    const float* w = Wout + (size_t)tag * (2 * HH);
    float acc = 0.0f;
    #pragma unroll 4
    for (int k = 0; k < 2 * HH; k += 4) {
        float4 wv = *reinterpret_cast<const float4*>(&w[k]);
        float4 hv = *reinterpret_cast<const float4*>(&hs[r][k]);
        acc += wv.x * hv.x + wv.y * hv.y + wv.z * hv.z + wv.w * hv.w;
    }
    feats[(size_t)(m0 + r) * KK + tag] = acc + bout[tag];
}

// ---------------- Viterbi: one block (32 threads) per batch row -----------------
__global__ __launch_bounds__(32) void viterbi_kernel(
    const float* __restrict__ feats, const float* __restrict__ trans,
    const float* __restrict__ startt, const float* __restrict__ stopt,
    float* __restrict__ out, int out_size)
{
    int b = blockIdx.x;
    int j = threadIdx.x;
    __shared__ unsigned char bp[TT - 1][KK];
    __shared__ int path[TT];

    float tr[KK];
    #pragma unroll
    for (int k = 0; k < KK; k++) tr[k] = trans[j * KK + k];

    float dp = startt[j] + feats[(size_t)b * KK + j];
    for (int t = 1; t < TT; t++) {
        float best = -INFINITY;
        int arg = 0;
        #pragma unroll
        for (int k = 0; k < KK; k++) {
            float v = tr[k] + __shfl_sync(0xffffffffu, dp, k);
            if (v > best) { best = v; arg = k; }
        }
        bp[t - 1][j] = (unsigned char)arg;
        dp = best + feats[((size_t)t * BB + b) * KK + j];
    }
    dp += stopt[j];

    float bv = dp; int bi = j;
    #pragma unroll
    for (int off = 16; off; off >>= 1) {
        float ov = __shfl_down_sync(0xffffffffu, bv, off);
        int   oi = __shfl_down_sync(0xffffffffu, bi, off);
        if (ov > bv || (ov == bv && oi < bi)) { bv = ov; bi = oi; }
    }
    bv = __shfl_sync(0xffffffffu, bv, 0);
    bi = __shfl_sync(0xffffffffu, bi, 0);

    if (j == 0) {
        path[TT - 1] = bi;
        int tag = bi;
        for (int t = TT - 2; t >= 0; t--) {
            tag = bp[t][tag];
            path[t] = tag;
        }
    }
    __syncwarp();

    int pathsOff = out_size - TT * BB;
    if (pathsOff >= (int)BB) {
        if (j == 0) out[b] = bv;
    } else if (pathsOff < 0) {
        if (j == 0 && b < out_size) out[b] = bv;
        return;
    }
    for (int t = j; t < TT; t += 32)
        out[pathsOff + t * BB + b] = (float)path[t];
}

// ---------------- launch ---------------------------------------------------------
extern "C" void kernel_launch(void* const* d_in, const int* in_sizes, int n_in,
                              void* d_out, int out_size) {
    const int*   sent    = (const int*)d_in[0];
    const float* emb     = (const float*)d_in[1];
    const float* wih_l0f = (const float*)d_in[2];
    const float* whh_l0f = (const float*)d_in[3];
    const float* bih_l0f = (const float*)d_in[4];
    const float* bhh_l0f = (const float*)d_in[5];
    const float* wih_l0r = (const float*)d_in[6];
    const float* whh_l0r = (const float*)d_in[7];
    const float* bih_l0r = (const float*)d_in[8];
    const float* bhh_l0r = (const float*)d_in[9];
    const float* wih_l1f = (const float*)d_in[10];
    const float* whh_l1f = (const float*)d_in[11];
    const float* bih_l1f = (const float*)d_in[12];
    const float* bhh_l1f = (const float*)d_in[13];
    const float* wih_l1r = (const float*)d_in[14];
    const float* whh_l1r = (const float*)d_in[15];
    const float* bih_l1r = (const float*)d_in[16];
    const float* bhh_l1r = (const float*)d_in[17];
    const float* W_out   = (const float*)d_in[18];
    const float* b_out   = (const float*)d_in[19];
    const float* transit = (const float*)d_in[20];
    const float* start_t = (const float*)d_in[21];
    const float* stop_t  = (const float*)d_in[22];

    float *xpf, *xpr, *hbuf, *feats, *hstate;
    unsigned* bar;
    cudaGetSymbolAddress((void**)&xpf,    g_xpf);
    cudaGetSymbolAddress((void**)&xpr,    g_xpr);
    cudaGetSymbolAddress((void**)&hbuf,   g_hbuf);
    cudaGetSymbolAddress((void**)&feats,  g_feats);
    cudaGetSymbolAddress((void**)&hstate, g_hstate);
    cudaGetSymbolAddress((void**)&bar,    g_bar);
    float *as, *hsx, *w0f, *w0r, *w1f, *w1r;
    cudaGetSymbolAddress((void**)&as,  g_as);
    cudaGetSymbolAddress((void**)&hsx, g_hs);
    cudaGetSymbolAddress((void**)&w0f, g_w0f);
    cudaGetSymbolAddress((void**)&w0r, g_w0r);
    cudaGetSymbolAddress((void**)&w1f, g_w1f);
    cudaGetSymbolAddress((void**)&w1r, g_w1r);
    const size_t ASZ = (size_t)MROWS*EE, HSZ = (size_t)MROWS*2*HH;
    const size_t W0SZ = (size_t)G4H*EE,  W1SZ = (size_t)G4H*2*HH;

    cudaFuncSetAttribute(lstm_layer_kernel,
                         cudaFuncAttributeMaxDynamicSharedMemorySize, LSTM_SMEM);
    cudaFuncSetAttribute(tf32_gemm,
                         cudaFuncAttributeMaxDynamicSharedMemorySize, GEMM_SMEM);

    // 1) embedding (fused gather + tf32 split)
    embed_split_kernel<<<(TT * BB * (EE / 4) + 255) / 256, 256>>>(
        sent, emb, as, as + ASZ);

    // 2) split layer-0 weights
    split2_kernel<<<(int)(W0SZ/4 + 255)/256, 256>>>(wih_l0f, w0f, w0f + W0SZ, (int)(W0SZ/4));
    split2_kernel<<<(int)(W0SZ/4 + 255)/256, 256>>>(wih_l0r, w0r, w0r + W0SZ, (int)(W0SZ/4));

    dim3 gg(G4H / 128, MROWS / 128);   // (16, 128)

    // 3) layer-0 input projections (tensor cores, 3xTF32)
    tf32_gemm<<<gg, 256, GEMM_SMEM>>>(as, as + ASZ, w0f, w0f + W0SZ,
                                      bih_l0f, bhh_l0f, xpf, EE);
    tf32_gemm<<<gg, 256, GEMM_SMEM>>>(as, as + ASZ, w0r, w0r + W0SZ,
                                      bih_l0r, bhh_l0r, xpr, EE);

    // 4) layer-0 recurrence
    cudaMemsetAsync(hstate, 0, sizeof(float) * 2 * 2 * BB * HH);
    cudaMemsetAsync(bar, 0, sizeof(unsigned) * 2);
    lstm_layer_kernel<<<128, 256, LSTM_SMEM>>>(xpf, xpr, whh_l0f, whh_l0r, hbuf, hstate, bar);

    // 5) split hbuf + layer-1 weights
    split2_kernel<<<(int)(HSZ/4 + 255)/256, 256>>>(hbuf, hsx, hsx + HSZ, (int)(HSZ/4));
    split2_kernel<<<(int)(W1SZ/4 + 255)/256, 256>>>(wih_l1f, w1f, w1f + W1SZ, (int)(W1SZ/4));
    split2_kernel<<<(int)(W1SZ/4 + 255)/256, 256>>>(wih_l1r, w1r, w1r + W1SZ, (int)(W1SZ/4));

    // 6) layer-1 input projections (tensor cores, K = 2H)
    tf32_gemm<<<gg, 256, GEMM_SMEM>>>(hsx, hsx + HSZ, w1f, w1f + W1SZ,
                                      bih_l1f, bhh_l1f, xpf, 2 * HH);
    tf32_gemm<<<gg, 256, GEMM_SMEM>>>(hsx, hsx + HSZ, w1r, w1r + W1SZ,
                                      bih_l1r, bhh_l1r, xpr, 2 * HH);

    // 7) layer-1 recurrence (overwrites hbuf)
    cudaMemsetAsync(hstate, 0, sizeof(float) * 2 * 2 * BB * HH);
    cudaMemsetAsync(bar, 0, sizeof(unsigned) * 2);
    lstm_layer_kernel<<<128, 256, LSTM_SMEM>>>(xpf, xpr, whh_l1f, whh_l1r, hbuf, hstate, bar);

    // 8) emissions
    feats_kernel<<<MROWS / 4, 128>>>(hbuf, W_out, b_out, feats);

    // 9) Viterbi decode + output write
    viterbi_kernel<<<BB, 32>>>(feats, transit, start_t, stop_t, (float*)d_out, out_size);
}

// round 6
// speedup vs baseline: 1.4166x; 1.2003x over previous
#include <cuda_runtime.h>
#include <cstdint>
#include <math.h>

#define TT 256
#define BB 64
#define EE 256
#define HH 512
#define KK 32
#define G4H 2048
#define MROWS (TT*BB)          // 16384

// ---------------- scratch (static device allocations; no cudaMalloc) ------------
__device__ float    g_xpf[MROWS*G4H];        // input proj fwd      (T,B,4H)
__device__ float    g_xpr[MROWS*G4H];        // input proj rev      (T,B,4H)
__device__ float    g_hbuf[MROWS*2*HH];      // layer output        (T,B,2H)
__device__ float    g_feats[MROWS*KK];       // emissions           (T,B,K)
__device__ float    g_hsthi[2*2*BB*HH];      // [buf][dir][B][H] h hi split
__device__ float    g_hstlo[2*2*BB*HH];      // [buf][dir][B][H] h lo split
__device__ unsigned g_bar[2];                // per-direction barrier counters
// tf32 hi/lo splits (fp32 bit patterns, tf32-rounded)
__device__ __align__(16) float g_as[2][MROWS*EE];      // embedded x splits
__device__ __align__(16) float g_hs[2][MROWS*2*HH];    // hbuf splits (written by lstm L0)
__device__ __align__(16) float g_w0f[2][G4H*EE];
__device__ __align__(16) float g_w0r[2][G4H*EE];
__device__ __align__(16) float g_w1f[2][G4H*2*HH];
__device__ __align__(16) float g_w1r[2][G4H*2*HH];

// single dynamic-smem symbol shared by all kernels
extern __shared__ __align__(16) char dynsmem[];

// ---------------- small helpers --------------------------------------------------
__device__ __forceinline__ float sigm(float x) { return 1.0f / (1.0f + expf(-x)); }

__device__ __forceinline__ void split_tf32(float x, float& hi, float& lo) {
    uint32_t h;
    asm("cvt.rna.tf32.f32 %0, %1;" : "=r"(h) : "f"(x));
    hi = __uint_as_float(h);
    float r = x - hi;
    uint32_t l;
    asm("cvt.rna.tf32.f32 %0, %1;" : "=r"(l) : "f"(r));
    lo = __uint_as_float(l);
}

__device__ __forceinline__ uint32_t smem_u32(const void* p) {
    uint32_t a;
    asm("{ .reg .u64 t; cvta.to.shared.u64 t, %1; cvt.u32.u64 %0, t; }"
        : "=r"(a) : "l"(p));
    return a;
}
__device__ __forceinline__ void cp16(uint32_t dst, const void* src) {
    asm volatile("cp.async.cg.shared.global [%0], [%1], 16;"
                 :: "r"(dst), "l"(src) : "memory");
}
__device__ __forceinline__ void cp_commit() {
    asm volatile("cp.async.commit_group;" ::: "memory");
}
__device__ __forceinline__ void cp_wait1() {
    asm volatile("cp.async.wait_group 1;" ::: "memory");
}
__device__ __forceinline__ void cp_wait0() {
    asm volatile("cp.async.wait_group 0;" ::: "memory");
}
__device__ __forceinline__ void mma_tf32(float* d, const uint32_t* a,
                                         uint32_t b0, uint32_t b1) {
    asm volatile(
        "mma.sync.aligned.m16n8k8.row.col.f32.tf32.tf32.f32 "
        "{%0,%1,%2,%3}, {%4,%5,%6,%7}, {%8,%9}, {%0,%1,%2,%3};"
        : "+f"(d[0]), "+f"(d[1]), "+f"(d[2]), "+f"(d[3])
        : "r"(a[0]), "r"(a[1]), "r"(a[2]), "r"(a[3]), "r"(b0), "r"(b1));
}

// ---------------- tf32 split of an fp32 array (float4 granularity) --------------
__global__ void split2_kernel(const float* __restrict__ in, float* __restrict__ oh,
                              float* __restrict__ ol, int n4) {
    int i = blockIdx.x * blockDim.x + threadIdx.x;
    if (i >= n4) return;
    float4 a = reinterpret_cast<const float4*>(in)[i];
    float4 h, l;
    split_tf32(a.x, h.x, l.x);
    split_tf32(a.y, h.y, l.y);
    split_tf32(a.z, h.z, l.z);
    split_tf32(a.w, h.w, l.w);
    reinterpret_cast<float4*>(oh)[i] = h;
    reinterpret_cast<float4*>(ol)[i] = l;
}

// ---------------- embedding gather fused with tf32 split ------------------------
__global__ void embed_split_kernel(const int* __restrict__ sent,
                                   const float* __restrict__ emb,
                                   float* __restrict__ oh, float* __restrict__ ol) {
    int i = blockIdx.x * blockDim.x + threadIdx.x;      // over T*B*(E/4)
    int total = TT * BB * (EE / 4);
    if (i >= total) return;
    int tb = i >> 6;
    int e4 = i & 63;
    int v = sent[tb];
    float4 a = reinterpret_cast<const float4*>(emb + (size_t)v * EE)[e4];
    float4 h, l;
    split_tf32(a.x, h.x, l.x);
    split_tf32(a.y, h.y, l.y);
    split_tf32(a.z, h.z, l.z);
    split_tf32(a.w, h.w, l.w);
    reinterpret_cast<float4*>(oh)[i] = h;
    reinterpret_cast<float4*>(ol)[i] = l;
}

// ---------------- 3xTF32 mma.sync GEMM (validated round 4) ----------------------
#define TPAD 20
#define TILE_F (128 * TPAD)
#define STAGE_F (4 * TILE_F)
#define GEMM_SMEM (2 * STAGE_F * 4)

__global__ __launch_bounds__(256) void tf32_gemm(
    const float* __restrict__ Ah, const float* __restrict__ Al,
    const float* __restrict__ Wh, const float* __restrict__ Wl,
    const float* __restrict__ bi1, const float* __restrict__ bi2,
    float* __restrict__ C, int K)
{
    float* smem = reinterpret_cast<float*>(dynsmem);
    const uint32_t sb = smem_u32(smem);
    const int tid = threadIdx.x, lane = tid & 31, wid = tid >> 5;
    const int wm = wid & 1, wn = wid >> 1;
    const int bn = blockIdx.x * 128, bm = blockIdx.y * 128;
    const int nch = K >> 4;
    const int qr = lane >> 2, qc = lane & 3;

    float acc[4][4][4];
    #pragma unroll
    for (int mi = 0; mi < 4; mi++)
        #pragma unroll
        for (int ni = 0; ni < 4; ni++)
            #pragma unroll
            for (int q = 0; q < 4; q++) acc[mi][ni][q] = 0.0f;

    auto issue = [&](int c, int st) {
        #pragma unroll
        for (int i = 0; i < 8; i++) {
            int s = tid + i * 256;
            int tile = s >> 9;
            int r = (s >> 2) & 127;
            int sub = s & 3;
            const float* g;
            if (tile == 0)      g = Ah + (size_t)(bm + r) * K + c * 16 + sub * 4;
            else if (tile == 1) g = Al + (size_t)(bm + r) * K + c * 16 + sub * 4;
            else if (tile == 2) g = Wh + (size_t)(bn + r) * K + c * 16 + sub * 4;
            else                g = Wl + (size_t)(bn + r) * K + c * 16 + sub * 4;
            uint32_t d = sb + (uint32_t)(st * STAGE_F + tile * TILE_F + r * TPAD + sub * 4) * 4;
            cp16(d, g);
        }
        cp_commit();
    };

    issue(0, 0);

    for (int c = 0; c < nch; c++) {
        const int st = c & 1;
        if (c + 1 < nch) { issue(c + 1, st ^ 1); cp_wait1(); }
        else cp_wait0();
        __syncthreads();

        const float* Ah_s = smem + st * STAGE_F;
        const float* Al_s = Ah_s + TILE_F;
        const float* Wh_s = Ah_s + 2 * TILE_F;
        const float* Wl_s = Ah_s + 3 * TILE_F;

        #pragma unroll
        for (int s8 = 0; s8 < 16; s8 += 8) {
            #pragma unroll
            for (int t = 0; t < 3; t++) {
                const float* At = (t == 2) ? Al_s : Ah_s;
                const float* Wt = (t == 1) ? Wl_s : Wh_s;
                uint32_t a[4][4];
                #pragma unroll
                for (int mi = 0; mi < 4; mi++) {
                    int m = wm * 64 + mi * 16 + qr;
                    const uint32_t* p =
                        reinterpret_cast<const uint32_t*>(At + m * TPAD + s8 + qc);
                    a[mi][0] = p[0];
                    a[mi][2] = p[4];
                    const uint32_t* p8 =
                        reinterpret_cast<const uint32_t*>(At + (m + 8) * TPAD + s8 + qc);
                    a[mi][1] = p8[0];
                    a[mi][3] = p8[4];
                }
                #pragma unroll
                for (int ni = 0; ni < 4; ni++) {
                    int n = wn * 32 + ni * 8 + qr;
                    const uint32_t* p =
                        reinterpret_cast<const uint32_t*>(Wt + n * TPAD + s8 + qc);
                    uint32_t b0 = p[0], b1 = p[4];
                    #pragma unroll
                    for (int mi = 0; mi < 4; mi++)
                        mma_tf32(acc[mi][ni], a[mi], b0, b1);
                }
            }
        }
        __syncthreads();
    }

    #pragma unroll
    for (int ni = 0; ni < 4; ni++) {
        int col = bn + wn * 32 + ni * 8 + 2 * qc;
        float2 s1 = *reinterpret_cast<const float2*>(bi1 + col);
        float2 s2 = *reinterpret_cast<const float2*>(bi2 + col);
        float bx = s1.x + s2.x, by = s1.y + s2.y;
        #pragma unroll
        for (int mi = 0; mi < 4; mi++) {
            int row = bm + wm * 64 + mi * 16 + qr;
            float2 v0 = make_float2(acc[mi][ni][0] + bx, acc[mi][ni][1] + by);
            float2 v1 = make_float2(acc[mi][ni][2] + bx, acc[mi][ni][3] + by);
            *reinterpret_cast<float2*>(&C[(size_t)row * G4H + col]) = v0;
            *reinterpret_cast<float2*>(&C[(size_t)(row + 8) * G4H + col]) = v1;
        }
    }
}

// ---------------- persistent LSTM layer, recurrent GEMM on tensor cores ---------
// 128 blocks (64/dir), 256 thr. Block owns 8 j-cols -> 32 W_hh rows (4 gates x 8 j).
// W_hh tf32-split in-kernel, resident in smem. h_prev hi/lo in global (L2-hot),
// cp.async-streamed in k=64 chunks, double buffered. 8 warps: 4 m-tiles x 2 n-halves,
// m16n8k8 x 3 tf32 terms. C staged through smem; cell update + tf32 re-split of h.
#define WP  516                      // W smem row stride (floats), conflict-free
#define HP  68                       // h chunk row stride (floats)
#define OFF_WLO (32*WP*4)            // 66048
#define OFF_H   (2*32*WP*4)          // 132096
#define HBUFB   (64*HP*4)            // 17408 bytes per (buf,term)
#define OFF_CS  (OFF_H + 4*HBUFB)    // 201728
#define LSTM2_SMEM (OFF_CS + 64*34*4)  // 210432 bytes

__global__ __launch_bounds__(256) void lstm_mma_kernel(
    const float* __restrict__ xpf, const float* __restrict__ xpr,
    const float* __restrict__ whf, const float* __restrict__ whr,
    float* __restrict__ hout, float* hsthi, float* hstlo,
    float* __restrict__ hb_hi, float* __restrict__ hb_lo,
    unsigned* bar, int dosplit)
{
    char* smem = dynsmem;
    float* Whi = reinterpret_cast<float*>(smem);
    float* Wlo = reinterpret_cast<float*>(smem + OFF_WLO);
    float* Cs  = reinterpret_cast<float*>(smem + OFF_CS);
    const uint32_t sb = smem_u32(smem);
    const int tid = threadIdx.x, lane = tid & 31, wid = tid >> 5;
    const int dir = blockIdx.x >> 6, sub = blockIdx.x & 63, j0 = sub * 8;
    const float* W  = dir ? whr : whf;
    const float* xp = dir ? xpr : xpf;
    const int qr = lane >> 2, qc = lane & 3;
    const int m0 = (wid & 3) * 16, nh = wid >> 2;

    // load + tf32-split W_hh slice (rows gate*512 + j0 + jl), row r = gate*8 + jl
    for (int i = tid; i < 32 * 512; i += 256) {
        int r = i >> 9, c = i & 511;
        int gate = r >> 3, jj = r & 7;
        float v = W[(size_t)(gate * 512 + j0 + jj) * HH + c];
        float hi, lo;
        split_tf32(v, hi, lo);
        Whi[r * WP + c] = hi;
        Wlo[r * WP + c] = lo;
    }
    __syncthreads();

    const int jl = tid & 7, b0 = tid >> 3, b1 = b0 + 32;
    const int j = j0 + jl;
    float c0 = 0.0f, c1 = 0.0f;

    for (int s = 0; s < TT; s++) {
        const int rb = s & 1, wb = rb ^ 1;
        const int tt = dir ? (TT - 1 - s) : s;
        const float* xpt = xp + (size_t)tt * BB * G4H;

        // prefetch input-projection gate values (DRAM)
        float xg[8];
        #pragma unroll
        for (int g = 0; g < 4; g++) {
            xg[g]     = xpt[b0 * G4H + g * HH + j];
            xg[g + 4] = xpt[b1 * G4H + g * HH + j];
        }

        const float* ghi = hsthi + (size_t)(rb * 2 + dir) * (BB * HH);
        const float* glo = hstlo + (size_t)(rb * 2 + dir) * (BB * HH);

        auto issue = [&](int c, int st) {
            uint32_t base = sb + OFF_H + (uint32_t)st * 2 * HBUFB;
            #pragma unroll
            for (int i = 0; i < 4; i++) {
                int sg = tid + i * 256;          // 1024 16B segments per term
                int row = sg >> 4, seg = sg & 15;
                uint32_t off = (uint32_t)(row * HP + seg * 4) * 4;
                const float* srch = ghi + (size_t)row * HH + c * 64 + seg * 4;
                const float* srcl = glo + (size_t)row * HH + c * 64 + seg * 4;
                cp16(base + off, srch);
                cp16(base + HBUFB + off, srcl);
            }
            cp_commit();
        };

        float acc[2][4] = {{0.f,0.f,0.f,0.f},{0.f,0.f,0.f,0.f}};
        issue(0, 0);
        for (int ch = 0; ch < 8; ch++) {
            const int st = ch & 1;
            if (ch < 7) { issue(ch + 1, st ^ 1); cp_wait1(); }
            else cp_wait0();
            __syncthreads();

            const uint32_t* Hh =
                reinterpret_cast<const uint32_t*>(smem + OFF_H + st * 2 * HBUFB);
            const uint32_t* Hl = Hh + 64 * HP;
            const uint32_t* Whu = reinterpret_cast<const uint32_t*>(Whi);
            const uint32_t* Wlu = reinterpret_cast<const uint32_t*>(Wlo);

            #pragma unroll
            for (int ko = 0; ko < 8; ko++) {
                const int c = ko * 8 + qc;
                uint32_t ah[4], al[4];
                ah[0] = Hh[(m0 + qr) * HP + c];
                ah[1] = Hh[(m0 + qr + 8) * HP + c];
                ah[2] = Hh[(m0 + qr) * HP + c + 4];
                ah[3] = Hh[(m0 + qr + 8) * HP + c + 4];
                al[0] = Hl[(m0 + qr) * HP + c];
                al[1] = Hl[(m0 + qr + 8) * HP + c];
                al[2] = Hl[(m0 + qr) * HP + c + 4];
                al[3] = Hl[(m0 + qr + 8) * HP + c + 4];
                const int kg = ch * 64 + ko * 8 + qc;
                #pragma unroll
                for (int nt = 0; nt < 2; nt++) {
                    const int n = nh * 16 + nt * 8 + qr;
                    uint32_t bh0 = Whu[n * WP + kg], bh1 = Whu[n * WP + kg + 4];
                    uint32_t bl0 = Wlu[n * WP + kg], bl1 = Wlu[n * WP + kg + 4];
                    mma_tf32(acc[nt], ah, bh0, bh1);
                    mma_tf32(acc[nt], al, bh0, bh1);
                    mma_tf32(acc[nt], ah, bl0, bl1);
                }
            }
            __syncthreads();
        }

        // stage C fragments -> smem (row b, col = gate*8 + jl)
        #pragma unroll
        for (int nt = 0; nt < 2; nt++) {
            int ncol = nh * 16 + nt * 8 + 2 * qc;
            *reinterpret_cast<float2*>(&Cs[(m0 + qr) * 34 + ncol]) =
                make_float2(acc[nt][0], acc[nt][1]);
            *reinterpret_cast<float2*>(&Cs[(m0 + qr + 8) * 34 + ncol]) =
                make_float2(acc[nt][2], acc[nt][3]);
        }
        __syncthreads();

        // cell update: thread owns (j = j0+jl, batches b0 and b0+32)
        float gi0 = Cs[b0 * 34 + 0 * 8 + jl] + xg[0];
        float gf0 = Cs[b0 * 34 + 1 * 8 + jl] + xg[1];
        float gg0 = Cs[b0 * 34 + 2 * 8 + jl] + xg[2];
        float go0 = Cs[b0 * 34 + 3 * 8 + jl] + xg[3];
        float gi1 = Cs[b1 * 34 + 0 * 8 + jl] + xg[4];
        float gf1 = Cs[b1 * 34 + 1 * 8 + jl] + xg[5];
        float gg1 = Cs[b1 * 34 + 2 * 8 + jl] + xg[6];
        float go1 = Cs[b1 * 34 + 3 * 8 + jl] + xg[7];

        c0 = sigm(gf0) * c0 + sigm(gi0) * tanhf(gg0);
        float h0v = sigm(go0) * tanhf(c0);
        c1 = sigm(gf1) * c1 + sigm(gi1) * tanhf(gg1);
        float h1v = sigm(go1) * tanhf(c1);

        float* dhi = hsthi + (size_t)(wb * 2 + dir) * (BB * HH);
        float* dlo = hstlo + (size_t)(wb * 2 + dir) * (BB * HH);
        float h0h, h0l, h1h, h1l;
        split_tf32(h0v, h0h, h0l);
        split_tf32(h1v, h1h, h1l);
        dhi[b0 * HH + j] = h0h; dlo[b0 * HH + j] = h0l;
        dhi[b1 * HH + j] = h1h; dlo[b1 * HH + j] = h1l;

        size_t o0 = (size_t)(tt * BB + b0) * (2 * HH) + dir * HH + j;
        size_t o1 = (size_t)(tt * BB + b1) * (2 * HH) + dir * HH + j;
        hout[o0] = h0v;
        hout[o1] = h1v;
        if (dosplit) {
            hb_hi[o0] = h0h; hb_lo[o0] = h0l;
            hb_hi[o1] = h1h; hb_lo[o1] = h1l;
        }

        __threadfence();
        __syncthreads();
        if (s + 1 < TT) {
            if (tid == 0) {
                atomicAdd(&bar[dir], 1u);
                unsigned target = 64u * (unsigned)(s + 1);
                volatile unsigned* p = bar + dir;
                while (*p < target) __nanosleep(64);
                __threadfence();
            }
            __syncthreads();
        }
    }
}

// ---------------- emissions: feats = hbuf @ W_out^T + b_out ---------------------
__global__ __launch_bounds__(128) void feats_kernel(
    const float* __restrict__ h, const float* __restrict__ Wout,
    const float* __restrict__ bout, float* __restrict__ feats)
{
    __shared__ __align__(16) float hs[4][2 * HH];
    int m0 = blockIdx.x * 4;
    int tid = threadIdx.x;
    for (int i = tid * 4; i < 4 * 2 * HH; i += 128 * 4)
        *reinterpret_cast<float4*>(&hs[0][i]) =
            *reinterpret_cast<const float4*>(&h[(size_t)m0 * 2 * HH + i]);
    __syncthreads();
    int r = tid >> 5, tag = tid & 31;
    const float* w = Wout + (size_t)tag * (2 * HH);
    float acc = 0.0f;
    #pragma unroll 4
    for (int k = 0; k < 2 * HH; k += 4) {
        float4 wv = *reinterpret_cast<const float4*>(&w[k]);
        float4 hv = *reinterpret_cast<const float4*>(&hs[r][k]);
        acc += wv.x * hv.x + wv.y * hv.y + wv.z * hv.z + wv.w * hv.w;
    }
    feats[(size_t)(m0 + r) * KK + tag] = acc + bout[tag];
}

// ---------------- Viterbi: one block (32 threads) per batch row -----------------
__global__ __launch_bounds__(32) void viterbi_kernel(
    const float* __restrict__ feats, const float* __restrict__ trans,
    const float* __restrict__ startt, const float* __restrict__ stopt,
    float* __restrict__ out, int out_size)
{
    int b = blockIdx.x;
    int j = threadIdx.x;
    __shared__ unsigned char bp[TT - 1][KK];
    __shared__ int path[TT];

    float tr[KK];
    #pragma unroll
    for (int k = 0; k < KK; k++) tr[k] = trans[j * KK + k];

    float dp = startt[j] + feats[(size_t)b * KK + j];
    for (int t = 1; t < TT; t++) {
        float best = -INFINITY;
        int arg = 0;
        #pragma unroll
        for (int k = 0; k < KK; k++) {
            float v = tr[k] + __shfl_sync(0xffffffffu, dp, k);
            if (v > best) { best = v; arg = k; }
        }
        bp[t - 1][j] = (unsigned char)arg;
        dp = best + feats[((size_t)t * BB + b) * KK + j];
    }
    dp += stopt[j];

    float bv = dp; int bi = j;
    #pragma unroll
    for (int off = 16; off; off >>= 1) {
        float ov = __shfl_down_sync(0xffffffffu, bv, off);
        int   oi = __shfl_down_sync(0xffffffffu, bi, off);
        if (ov > bv || (ov == bv && oi < bi)) { bv = ov; bi = oi; }
    }
    bv = __shfl_sync(0xffffffffu, bv, 0);
    bi = __shfl_sync(0xffffffffu, bi, 0);

    if (j == 0) {
        path[TT - 1] = bi;
        int tag = bi;
        for (int t = TT - 2; t >= 0; t--) {
            tag = bp[t][tag];
            path[t] = tag;
        }
    }
    __syncwarp();

    int pathsOff = out_size - TT * BB;
    if (pathsOff >= (int)BB) {
        if (j == 0) out[b] = bv;
    } else if (pathsOff < 0) {
        if (j == 0 && b < out_size) out[b] = bv;
        return;
    }
    for (int t = j; t < TT; t += 32)
        out[pathsOff + t * BB + b] = (float)path[t];
}

// ---------------- launch ---------------------------------------------------------
extern "C" void kernel_launch(void* const* d_in, const int* in_sizes, int n_in,
                              void* d_out, int out_size) {
    const int*   sent    = (const int*)d_in[0];
    const float* emb     = (const float*)d_in[1];
    const float* wih_l0f = (const float*)d_in[2];
    const float* whh_l0f = (const float*)d_in[3];
    const float* bih_l0f = (const float*)d_in[4];
    const float* bhh_l0f = (const float*)d_in[5];
    const float* wih_l0r = (const float*)d_in[6];
    const float* whh_l0r = (const float*)d_in[7];
    const float* bih_l0r = (const float*)d_in[8];
    const float* bhh_l0r = (const float*)d_in[9];
    const float* wih_l1f = (const float*)d_in[10];
    const float* whh_l1f = (const float*)d_in[11];
    const float* bih_l1f = (const float*)d_in[12];
    const float* bhh_l1f = (const float*)d_in[13];
    const float* wih_l1r = (const float*)d_in[14];
    const float* whh_l1r = (const float*)d_in[15];
    const float* bih_l1r = (const float*)d_in[16];
    const float* bhh_l1r = (const float*)d_in[17];
    const float* W_out   = (const float*)d_in[18];
    const float* b_out   = (const float*)d_in[19];
    const float* transit = (const float*)d_in[20];
    const float* start_t = (const float*)d_in[21];
    const float* stop_t  = (const float*)d_in[22];

    float *xpf, *xpr, *hbuf, *feats, *hsthi, *hstlo;
    unsigned* bar;
    cudaGetSymbolAddress((void**)&xpf,   g_xpf);
    cudaGetSymbolAddress((void**)&xpr,   g_xpr);
    cudaGetSymbolAddress((void**)&hbuf,  g_hbuf);
    cudaGetSymbolAddress((void**)&feats, g_feats);
    cudaGetSymbolAddress((void**)&hsthi, g_hsthi);
    cudaGetSymbolAddress((void**)&hstlo, g_hstlo);
    cudaGetSymbolAddress((void**)&bar,   g_bar);
    float *as, *hsx, *w0f, *w0r, *w1f, *w1r;
    cudaGetSymbolAddress((void**)&as,  g_as);
    cudaGetSymbolAddress((void**)&hsx, g_hs);
    cudaGetSymbolAddress((void**)&w0f, g_w0f);
    cudaGetSymbolAddress((void**)&w0r, g_w0r);
    cudaGetSymbolAddress((void**)&w1f, g_w1f);
    cudaGetSymbolAddress((void**)&w1r, g_w1r);
    const size_t ASZ = (size_t)MROWS*EE, HSZ = (size_t)MROWS*2*HH;
    const size_t W0SZ = (size_t)G4H*EE,  W1SZ = (size_t)G4H*2*HH;

    cudaFuncSetAttribute(tf32_gemm,
                         cudaFuncAttributeMaxDynamicSharedMemorySize, GEMM_SMEM);
    cudaFuncSetAttribute(lstm_mma_kernel,
                         cudaFuncAttributeMaxDynamicSharedMemorySize, LSTM2_SMEM);

    // 1) embedding (fused gather + tf32 split)
    embed_split_kernel<<<(TT * BB * (EE / 4) + 255) / 256, 256>>>(
        sent, emb, as, as + ASZ);

    // 2) split input-projection weights (all independent of the pipeline)
    split2_kernel<<<(int)(W0SZ/4 + 255)/256, 256>>>(wih_l0f, w0f, w0f + W0SZ, (int)(W0SZ/4));
    split2_kernel<<<(int)(W0SZ/4 + 255)/256, 256>>>(wih_l0r, w0r, w0r + W0SZ, (int)(W0SZ/4));
    split2_kernel<<<(int)(W1SZ/4 + 255)/256, 256>>>(wih_l1f, w1f, w1f + W1SZ, (int)(W1SZ/4));
    split2_kernel<<<(int)(W1SZ/4 + 255)/256, 256>>>(wih_l1r, w1r, w1r + W1SZ, (int)(W1SZ/4));

    dim3 gg(G4H / 128, MROWS / 128);   // (16, 128)

    // 3) layer-0 input projections (tensor cores, 3xTF32)
    tf32_gemm<<<gg, 256, GEMM_SMEM>>>(as, as + ASZ, w0f, w0f + W0SZ,
                                      bih_l0f, bhh_l0f, xpf, EE);
    tf32_gemm<<<gg, 256, GEMM_SMEM>>>(as, as + ASZ, w0r, w0r + W0SZ,
                                      bih_l0r, bhh_l0r, xpr, EE);

    // 4) layer-0 recurrence (tensor cores); writes hbuf + its tf32 splits
    cudaMemsetAsync(hsthi, 0, sizeof(float) * 2 * 2 * BB * HH);
    cudaMemsetAsync(hstlo, 0, sizeof(float) * 2 * 2 * BB * HH);
    cudaMemsetAsync(bar, 0, sizeof(unsigned) * 2);
    lstm_mma_kernel<<<128, 256, LSTM2_SMEM>>>(xpf, xpr, whh_l0f, whh_l0r,
                                              hbuf, hsthi, hstlo,
                                              hsx, hsx + HSZ, bar, 1);

    // 5) layer-1 input projections (K = 2H), A = hbuf splits from step 4
    tf32_gemm<<<gg, 256, GEMM_SMEM>>>(hsx, hsx + HSZ, w1f, w1f + W1SZ,
                                      bih_l1f, bhh_l1f, xpf, 2 * HH);
    tf32_gemm<<<gg, 256, GEMM_SMEM>>>(hsx, hsx + HSZ, w1r, w1r + W1SZ,
                                      bih_l1r, bhh_l1r, xpr, 2 * HH);

    // 6) layer-1 recurrence (overwrites hbuf; no splits needed)
    cudaMemsetAsync(hsthi, 0, sizeof(float) * 2 * 2 * BB * HH);
    cudaMemsetAsync(hstlo, 0, sizeof(float) * 2 * 2 * BB * HH);
    cudaMemsetAsync(bar, 0, sizeof(unsigned) * 2);
    lstm_mma_kernel<<<128, 256, LSTM2_SMEM>>>(xpf, xpr, whh_l1f, whh_l1r,
                                              hbuf, hsthi, hstlo,
                                              hsx, hsx + HSZ, bar, 0);

    // 7) emissions
    feats_kernel<<<MROWS / 4, 128>>>(hbuf, W_out, b_out, feats);

    // 8) Viterbi decode + output write
    viterbi_kernel<<<BB, 32>>>(feats, transit, start_t, stop_t, (float*)d_out, out_size);
}